// round 2
// baseline (speedup 1.0000x reference)
#include <cuda_runtime.h>
#include <cuda_bf16.h>
#include <cstdint>

// Problem constants
#define L_DIM 1024
#define B_DIM 8
#define E_DIM 1024
#define H_DIM 16
#define HD 64
#define M_DIM (L_DIM * B_DIM)      // 8192
#define NQKV (3 * E_DIM)           // 3072
#define BH (B_DIM * H_DIM)         // 128
#define SCALING 0.125f             // hd^-0.5

// Scratch (device globals; no allocation allowed)
__device__ float g_q[(size_t)BH * L_DIM * HD];    // [bh][l][d]
__device__ float g_k[(size_t)BH * L_DIM * HD];
__device__ float g_v[(size_t)BH * L_DIM * HD];
__device__ float g_att[(size_t)M_DIM * E_DIM];    // [m][e], m = l*B+b

// ---------------------------------------------------------------------------
// GEMM 1: qkv = X @ W^T + bias, epilogue scatters into head-major q/k/v
// X: [8192,1024] row-major, W: [3072,1024] row-major (so NT gemm, dot over k)
// ---------------------------------------------------------------------------
#define BM 128
#define BN 128
#define BKK 16
#define TM 8
#define TN 8

__global__ __launch_bounds__(256) void qkv_gemm_kernel(
    const float* __restrict__ X, const float* __restrict__ W,
    const float* __restrict__ bias)
{
    __shared__ float As[BKK][BM];
    __shared__ float Bs[BKK][BN];

    const int m0 = blockIdx.y * BM;
    const int n0 = blockIdx.x * BN;
    const int t  = threadIdx.x;
    const int tx = t & 15;
    const int ty = t >> 4;

    float acc[TM][TN];
#pragma unroll
    for (int i = 0; i < TM; i++)
#pragma unroll
        for (int j = 0; j < TN; j++) acc[i][j] = 0.0f;

    for (int k0 = 0; k0 < E_DIM; k0 += BKK) {
#pragma unroll
        for (int u = 0; u < 2; u++) {
            int f   = t + 256 * u;        // 0..511
            int row = f >> 2;             // 0..127
            int c4  = (f & 3) * 4;        // 0,4,8,12
            float4 va = *(const float4*)(X + (size_t)(m0 + row) * E_DIM + k0 + c4);
            As[c4 + 0][row] = va.x; As[c4 + 1][row] = va.y;
            As[c4 + 2][row] = va.z; As[c4 + 3][row] = va.w;
            float4 vb = *(const float4*)(W + (size_t)(n0 + row) * E_DIM + k0 + c4);
            Bs[c4 + 0][row] = vb.x; Bs[c4 + 1][row] = vb.y;
            Bs[c4 + 2][row] = vb.z; Bs[c4 + 3][row] = vb.w;
        }
        __syncthreads();

#pragma unroll
        for (int kk = 0; kk < BKK; kk++) {
            float a[TM], b[TN];
            *(float4*)&a[0] = *(const float4*)&As[kk][ty * TM];
            *(float4*)&a[4] = *(const float4*)&As[kk][ty * TM + 4];
            *(float4*)&b[0] = *(const float4*)&Bs[kk][tx * TN];
            *(float4*)&b[4] = *(const float4*)&Bs[kk][tx * TN + 4];
#pragma unroll
            for (int i = 0; i < TM; i++)
#pragma unroll
                for (int j = 0; j < TN; j++) acc[i][j] = fmaf(a[i], b[j], acc[i][j]);
        }
        __syncthreads();
    }

    // Epilogue: add bias, scatter to head-major q/k/v; scale q.
#pragma unroll
    for (int i = 0; i < TM; i++) {
        int m = m0 + ty * TM + i;
        int b = m & (B_DIM - 1);
        int l = m >> 3;
#pragma unroll
        for (int j = 0; j < TN; j++) {
            int n = n0 + tx * TN + j;
            float val = acc[i][j] + bias[n];
            int sec = n >> 10;       // 0=q,1=k,2=v
            int e   = n & 1023;
            int h   = e >> 6;
            int d   = e & 63;
            size_t dst = ((size_t)(b * H_DIM + h) * L_DIM + l) * HD + d;
            if (sec == 0)      g_q[dst] = val * SCALING;
            else if (sec == 1) g_k[dst] = val;
            else               g_v[dst] = val;
        }
    }
}

// ---------------------------------------------------------------------------
// Flash attention (fp32, online softmax).
// Grid: (BH=128, L/64=16). Block 256 threads (16x16), each thread 4x4.
// smem: Qt[d][l] (transposed), KP = Kt[d][j] then reused as Pt[j][row],
//       Vs[j][d]. Exactly 48KB static.
// ---------------------------------------------------------------------------
__global__ __launch_bounds__(256) void attn_kernel()
{
    __shared__ float Qt[64][64];
    __shared__ float KP[64][64];
    __shared__ float Vs[64][64];

    const int bh = blockIdx.x;
    const int q0 = blockIdx.y * 64;
    const int t  = threadIdx.x;
    const int tx = t & 15;
    const int ty = t >> 4;

    const float* Qg = g_q + ((size_t)bh * L_DIM + q0) * HD;
    const float* Kg = g_k + (size_t)bh * L_DIM * HD;
    const float* Vg = g_v + (size_t)bh * L_DIM * HD;

    // Load Q tile transposed: Qt[d][row]
#pragma unroll
    for (int u = 0; u < 4; u++) {
        int f   = t + 256 * u;     // 0..1023
        int row = f >> 4;          // 0..63
        int d0  = (f & 15) * 4;
        float4 v = *(const float4*)(Qg + (size_t)row * HD + d0);
        Qt[d0 + 0][row] = v.x; Qt[d0 + 1][row] = v.y;
        Qt[d0 + 2][row] = v.z; Qt[d0 + 3][row] = v.w;
    }

    float m_i[4], l_i[4], O[4][4];
#pragma unroll
    for (int i = 0; i < 4; i++) {
        m_i[i] = -1e30f; l_i[i] = 0.0f;
#pragma unroll
        for (int j = 0; j < 4; j++) O[i][j] = 0.0f;
    }

    for (int kt = 0; kt < L_DIM / 64; kt++) {
        __syncthreads();   // previous PV done reading KP/Vs (and first-iter noop)

        // Load K transposed + V row-major
#pragma unroll
        for (int u = 0; u < 4; u++) {
            int f   = t + 256 * u;
            int row = f >> 4;
            int d0  = (f & 15) * 4;
            const float* kp = Kg + ((size_t)(kt * 64 + row)) * HD + d0;
            float4 v = *(const float4*)kp;
            KP[d0 + 0][row] = v.x; KP[d0 + 1][row] = v.y;
            KP[d0 + 2][row] = v.z; KP[d0 + 3][row] = v.w;
            const float* vp = Vg + ((size_t)(kt * 64 + row)) * HD + d0;
            *(float4*)&Vs[row][d0] = *(const float4*)vp;
        }
        __syncthreads();

        // S = Q K^T  (dot over d)
        float s[4][4];
#pragma unroll
        for (int i = 0; i < 4; i++)
#pragma unroll
            for (int j = 0; j < 4; j++) s[i][j] = 0.0f;

#pragma unroll
        for (int kk = 0; kk < 64; kk++) {
            float4 qa = *(const float4*)&Qt[kk][ty * 4];
            float4 kb = *(const float4*)&KP[kk][tx * 4];
            const float qv[4] = {qa.x, qa.y, qa.z, qa.w};
            const float kv[4] = {kb.x, kb.y, kb.z, kb.w};
#pragma unroll
            for (int i = 0; i < 4; i++)
#pragma unroll
                for (int j = 0; j < 4; j++) s[i][j] = fmaf(qv[i], kv[j], s[i][j]);
        }

        // Online softmax (rows owned across the 16-lane tx group)
#pragma unroll
        for (int i = 0; i < 4; i++) {
            float lm = fmaxf(fmaxf(s[i][0], s[i][1]), fmaxf(s[i][2], s[i][3]));
#pragma unroll
            for (int off = 8; off >= 1; off >>= 1)
                lm = fmaxf(lm, __shfl_xor_sync(0xffffffffu, lm, off));
            float mn = fmaxf(m_i[i], lm);
            float corr = __expf(m_i[i] - mn);
            float rs = 0.0f;
#pragma unroll
            for (int j = 0; j < 4; j++) {
                s[i][j] = __expf(s[i][j] - mn);
                rs += s[i][j];
            }
#pragma unroll
            for (int off = 8; off >= 1; off >>= 1)
                rs += __shfl_xor_sync(0xffffffffu, rs, off);
            l_i[i] = l_i[i] * corr + rs;
            m_i[i] = mn;
#pragma unroll
            for (int j = 0; j < 4; j++) O[i][j] *= corr;
        }

        __syncthreads();   // everyone done reading KP as K

        // Write P transposed: Pt[j][row]
#pragma unroll
        for (int i = 0; i < 4; i++)
#pragma unroll
            for (int j = 0; j < 4; j++)
                KP[tx * 4 + j][ty * 4 + i] = s[i][j];
        __syncthreads();

        // O += P @ V
#pragma unroll
        for (int j64 = 0; j64 < 64; j64++) {
            float4 pa = *(const float4*)&KP[j64][ty * 4];
            float4 vb = *(const float4*)&Vs[j64][tx * 4];
            const float pv[4] = {pa.x, pa.y, pa.z, pa.w};
            const float vv[4] = {vb.x, vb.y, vb.z, vb.w};
#pragma unroll
            for (int i = 0; i < 4; i++)
#pragma unroll
                for (int j = 0; j < 4; j++) O[i][j] = fmaf(pv[i], vv[j], O[i][j]);
        }
    }

    // Epilogue: normalize and write att_out[m][e] with m = l*B+b, e = h*64+d
    const int b = bh >> 4;
    const int h = bh & 15;
#pragma unroll
    for (int i = 0; i < 4; i++) {
        float inv = 1.0f / l_i[i];
        int l = q0 + ty * 4 + i;
        size_t m = (size_t)l * B_DIM + b;
        float4 o4 = make_float4(O[i][0] * inv, O[i][1] * inv,
                                O[i][2] * inv, O[i][3] * inv);
        *(float4*)(g_att + m * E_DIM + h * HD + tx * 4) = o4;
    }
}

// ---------------------------------------------------------------------------
// GEMM 2: out = att @ Wout^T + bout, direct store to d_out ([L,B,E] == [m][e])
// ---------------------------------------------------------------------------
__global__ __launch_bounds__(256) void out_gemm_kernel(
    const float* __restrict__ W, const float* __restrict__ bias,
    float* __restrict__ out)
{
    __shared__ float As[BKK][BM];
    __shared__ float Bs[BKK][BN];

    const int m0 = blockIdx.y * BM;
    const int n0 = blockIdx.x * BN;
    const int t  = threadIdx.x;
    const int tx = t & 15;
    const int ty = t >> 4;

    float acc[TM][TN];
#pragma unroll
    for (int i = 0; i < TM; i++)
#pragma unroll
        for (int j = 0; j < TN; j++) acc[i][j] = 0.0f;

    for (int k0 = 0; k0 < E_DIM; k0 += BKK) {
#pragma unroll
        for (int u = 0; u < 2; u++) {
            int f   = t + 256 * u;
            int row = f >> 2;
            int c4  = (f & 3) * 4;
            float4 va = *(const float4*)(g_att + (size_t)(m0 + row) * E_DIM + k0 + c4);
            As[c4 + 0][row] = va.x; As[c4 + 1][row] = va.y;
            As[c4 + 2][row] = va.z; As[c4 + 3][row] = va.w;
            float4 vb = *(const float4*)(W + (size_t)(n0 + row) * E_DIM + k0 + c4);
            Bs[c4 + 0][row] = vb.x; Bs[c4 + 1][row] = vb.y;
            Bs[c4 + 2][row] = vb.z; Bs[c4 + 3][row] = vb.w;
        }
        __syncthreads();

#pragma unroll
        for (int kk = 0; kk < BKK; kk++) {
            float a[TM], b[TN];
            *(float4*)&a[0] = *(const float4*)&As[kk][ty * TM];
            *(float4*)&a[4] = *(const float4*)&As[kk][ty * TM + 4];
            *(float4*)&b[0] = *(const float4*)&Bs[kk][tx * TN];
            *(float4*)&b[4] = *(const float4*)&Bs[kk][tx * TN + 4];
#pragma unroll
            for (int i = 0; i < TM; i++)
#pragma unroll
                for (int j = 0; j < TN; j++) acc[i][j] = fmaf(a[i], b[j], acc[i][j]);
        }
        __syncthreads();
    }

#pragma unroll
    for (int i = 0; i < TM; i++) {
        int m = m0 + ty * TM + i;
#pragma unroll
        for (int j = 0; j < TN; j += 4) {
            int n = n0 + tx * TN + j;
            float4 o4 = make_float4(acc[i][j]     + bias[n],
                                    acc[i][j + 1] + bias[n + 1],
                                    acc[i][j + 2] + bias[n + 2],
                                    acc[i][j + 3] + bias[n + 3]);
            *(float4*)(out + (size_t)m * E_DIM + n) = o4;
        }
    }
}

// ---------------------------------------------------------------------------
// Inputs (metadata order): x, in_proj_weight, in_proj_bias, out_proj_weight,
//                          out_proj_bias, num_heads
// ---------------------------------------------------------------------------
extern "C" void kernel_launch(void* const* d_in, const int* in_sizes, int n_in,
                              void* d_out, int out_size)
{
    const float* x     = (const float*)d_in[0];
    const float* wqkv  = (const float*)d_in[1];
    const float* bqkv  = (const float*)d_in[2];
    const float* wout  = (const float*)d_in[3];
    const float* bout  = (const float*)d_in[4];
    float* out = (float*)d_out;

    {
        dim3 grid(NQKV / BN, M_DIM / BM);   // (24, 64)
        qkv_gemm_kernel<<<grid, 256>>>(x, wqkv, bqkv);
    }
    {
        dim3 grid(BH, L_DIM / 64);          // (128, 16)
        attn_kernel<<<grid, 256>>>();
    }
    {
        dim3 grid(E_DIM / BN, M_DIM / BM);  // (8, 64)
        out_gemm_kernel<<<grid, 256>>>(wout, bout, out);
    }
}

// round 10
// speedup vs baseline: 1.6044x; 1.6044x over previous
#include <cuda_runtime.h>
#include <cuda_bf16.h>
#include <cstdint>

// Problem constants
#define L_DIM 1024
#define B_DIM 8
#define E_DIM 1024
#define H_DIM 16
#define HD 64
#define M_DIM (L_DIM * B_DIM)      // 8192
#define NQKV (3 * E_DIM)           // 3072
#define BH (B_DIM * H_DIM)         // 128
#define SCALING 0.125f             // hd^-0.5

// ---------------------------------------------------------------------------
// Scratch (device globals; no allocation allowed)
// ---------------------------------------------------------------------------
__device__ float g_q[(size_t)BH * L_DIM * HD];    // [bh][l][d] (scaled)
__device__ float g_k[(size_t)BH * L_DIM * HD];
__device__ float g_v[(size_t)BH * L_DIM * HD];

// bf16 hi/lo splits for tensor-core GEMMs
__device__ __nv_bfloat16 g_xh[(size_t)M_DIM * E_DIM];
__device__ __nv_bfloat16 g_xl[(size_t)M_DIM * E_DIM];
__device__ __nv_bfloat16 g_w1h[(size_t)NQKV * E_DIM];
__device__ __nv_bfloat16 g_w1l[(size_t)NQKV * E_DIM];
__device__ __nv_bfloat16 g_ah[(size_t)M_DIM * E_DIM];   // attention out hi
__device__ __nv_bfloat16 g_al[(size_t)M_DIM * E_DIM];   // attention out lo
__device__ __nv_bfloat16 g_w2h[(size_t)E_DIM * E_DIM];
__device__ __nv_bfloat16 g_w2l[(size_t)E_DIM * E_DIM];

// ---------------------------------------------------------------------------
// Helpers (arch-agnostic: mma.sync / ldmatrix / cp.async only; NO tcgen05)
// ---------------------------------------------------------------------------
static __device__ __forceinline__ uint32_t smem_u32(const void* p) {
    uint32_t a;
    asm("{ .reg .u64 t; cvta.to.shared.u64 t, %1; cvt.u32.u64 %0, t; }"
        : "=r"(a) : "l"(p));
    return a;
}

static __device__ __forceinline__ void ldsm4(uint32_t* r, uint32_t a) {
    asm volatile("ldmatrix.sync.aligned.m8n8.x4.shared.b16 {%0,%1,%2,%3}, [%4];"
                 : "=r"(r[0]), "=r"(r[1]), "=r"(r[2]), "=r"(r[3]) : "r"(a));
}

static __device__ __forceinline__ void mma_bf16(float* c, const uint32_t* a,
                                                const uint32_t* b) {
    asm volatile(
        "mma.sync.aligned.m16n8k16.row.col.f32.bf16.bf16.f32 "
        "{%0,%1,%2,%3}, {%4,%5,%6,%7}, {%8,%9}, {%0,%1,%2,%3};"
        : "+f"(c[0]), "+f"(c[1]), "+f"(c[2]), "+f"(c[3])
        : "r"(a[0]), "r"(a[1]), "r"(a[2]), "r"(a[3]), "r"(b[0]), "r"(b[1]));
}

#define CP_ASYNC16(sa, gp) \
    asm volatile("cp.async.cg.shared.global [%0], [%1], 16;" :: "r"(sa), "l"(gp))
#define CP_COMMIT() asm volatile("cp.async.commit_group;" ::: "memory")
#define CP_WAIT1()  asm volatile("cp.async.wait_group 1;" ::: "memory")
#define CP_WAIT0()  asm volatile("cp.async.wait_group 0;" ::: "memory")

// ---------------------------------------------------------------------------
// fp32 -> bf16 hi/lo split
// ---------------------------------------------------------------------------
__global__ __launch_bounds__(256) void split_kernel(
    const float* __restrict__ src, __nv_bfloat16* __restrict__ hi,
    __nv_bfloat16* __restrict__ lo, int n)
{
    int i = blockIdx.x * blockDim.x + threadIdx.x;
    if (i < n) {
        float x = src[i];
        __nv_bfloat16 h = __float2bfloat16(x);
        float r = x - __bfloat162float(h);
        hi[i] = h;
        lo[i] = __float2bfloat16(r);
    }
}

// ---------------------------------------------------------------------------
// HMMA bf16-split GEMM: D[m][n] = sum_k A[m][k]*B[n][k] (+bias epilogue)
// CTA tile 128x128, BK=32, 256 threads (8 warps, warp tile 64x32).
// smem tiles: 128 rows x 64B with 16B-chunk swizzle c ^= (row>>1)&3
// (conflict-free for cp.async stores AND all ldmatrix phases).
// 3 passes per k-step: AhBh + AhBl + AlBh  (fp32 accumulate).
// EPI=0: scatter into g_q/g_k/g_v head layout. EPI=1: write out[m][n].
// ---------------------------------------------------------------------------
#define GTILE 8192                     // one 128x32 bf16 tile = 8KB
#define STAGE (4 * GTILE)              // Ah, Al, Bh, Bl = 32KB
#define GEMM_SMEM 66048                // max(2*STAGE=65536, 128*129*4=66048)

template <int EPI>
__global__ __launch_bounds__(256) void hmma_gemm_kernel(
    const __nv_bfloat16* __restrict__ Ah, const __nv_bfloat16* __restrict__ Al,
    const __nv_bfloat16* __restrict__ Bh, const __nv_bfloat16* __restrict__ Bl,
    const float* __restrict__ bias, float* __restrict__ out, int Kdim)
{
    extern __shared__ char smem[];
    const uint32_t sbase = smem_u32(smem);
    const int tid  = threadIdx.x;
    const int lane = tid & 31;
    const int w    = tid >> 5;
    const int wm   = (w >> 2) * 64;     // warp m offset in tile
    const int wn   = (w & 3) * 32;      // warp n offset in tile
    const int m0   = blockIdx.y * 128;
    const int n0   = blockIdx.x * 128;

    const __nv_bfloat16* gbase[4] = {
        Ah + (size_t)m0 * Kdim, Al + (size_t)m0 * Kdim,
        Bh + (size_t)n0 * Kdim, Bl + (size_t)n0 * Kdim };

    // ldmatrix per-lane row/half decomposition
    const int arow  = lane & 15;        // A: rows m..m+15
    const int ahalf = lane >> 4;        // A: k-chunk half
    const int brow  = ((lane >> 4) << 3) + (lane & 7);  // B: n row
    const int bhalf = (lane >> 3) & 1;  // B: k-chunk half

    float acc[4][4][4];
#pragma unroll
    for (int i = 0; i < 4; i++)
#pragma unroll
        for (int j = 0; j < 4; j++)
#pragma unroll
            for (int e = 0; e < 4; e++) acc[i][j][e] = 0.0f;

    const int nchunk = Kdim / 32;       // 32

    // -------- async stage loader --------
    auto load_stage = [&](int c, int s) {
        const uint32_t st = sbase + s * STAGE;
        const int k0 = c * 32;
#pragma unroll
        for (int i = 0; i < 8; i++) {
            int f   = tid + 256 * i;
            int t   = f >> 9;           // which of 4 tiles
            int g   = f & 511;
            int row = g >> 2;
            int cc  = g & 3;
            int csw = cc ^ ((row >> 1) & 3);
            const void* gp = gbase[t] + (size_t)row * Kdim + k0 + cc * 8;
            uint32_t sa = st + t * GTILE + (uint32_t)(row * 4 + csw) * 16;
            CP_ASYNC16(sa, gp);
        }
        CP_COMMIT();
    };

    // -------- compute one 32-wide k chunk --------
    auto compute_stage = [&](int s) {
        const uint32_t st  = sbase + s * STAGE;
        const uint32_t tAh = st, tAl = st + GTILE;
        const uint32_t tBh = st + 2 * GTILE, tBl = st + 3 * GTILE;
#pragma unroll
        for (int ks = 0; ks < 2; ks++) {
            const int cb = ks * 2;
            uint32_t Ahf[4][4], Alf[4][4], Bhf[4][2], Blf[4][2];
#pragma unroll
            for (int mi = 0; mi < 4; mi++) {
                int row = wm + mi * 16 + arow;
                uint32_t u = (uint32_t)(row * 4 + ((ahalf ^ ((row >> 1) & 3)) ^ cb)) * 16;
                ldsm4(Ahf[mi], tAh + u);
                ldsm4(Alf[mi], tAl + u);
            }
#pragma unroll
            for (int j2 = 0; j2 < 2; j2++) {
                int row = wn + j2 * 16 + brow;
                uint32_t u = (uint32_t)(row * 4 + ((bhalf ^ ((row >> 1) & 3)) ^ cb)) * 16;
                uint32_t r[4];
                ldsm4(r, tBh + u);
                Bhf[j2 * 2][0] = r[0]; Bhf[j2 * 2][1] = r[1];
                Bhf[j2 * 2 + 1][0] = r[2]; Bhf[j2 * 2 + 1][1] = r[3];
                ldsm4(r, tBl + u);
                Blf[j2 * 2][0] = r[0]; Blf[j2 * 2][1] = r[1];
                Blf[j2 * 2 + 1][0] = r[2]; Blf[j2 * 2 + 1][1] = r[3];
            }
#pragma unroll
            for (int mi = 0; mi < 4; mi++)
#pragma unroll
                for (int nj = 0; nj < 4; nj++) {
                    mma_bf16(acc[mi][nj], Ahf[mi], Bhf[nj]);
                    mma_bf16(acc[mi][nj], Ahf[mi], Blf[nj]);
                    mma_bf16(acc[mi][nj], Alf[mi], Bhf[nj]);
                }
        }
    };

    // -------- pipelined mainloop --------
    load_stage(0, 0);
#pragma unroll 1
    for (int c = 0; c < nchunk; c++) {
        if (c + 1 < nchunk) { load_stage(c + 1, (c + 1) & 1); CP_WAIT1(); }
        else                { CP_WAIT0(); }
        __syncthreads();
        compute_stage(c & 1);
        __syncthreads();
    }

    // -------- stage D into smem (padded, conflict-free) --------
    float* sf = (float*)smem;
#pragma unroll
    for (int mi = 0; mi < 4; mi++) {
        int r = wm + mi * 16 + (lane >> 2);
#pragma unroll
        for (int nj = 0; nj < 4; nj++) {
            int col = wn + nj * 8 + (lane & 3) * 2;
            sf[r * 129 + col]           = acc[mi][nj][0];
            sf[r * 129 + col + 1]       = acc[mi][nj][1];
            sf[(r + 8) * 129 + col]     = acc[mi][nj][2];
            sf[(r + 8) * 129 + col + 1] = acc[mi][nj][3];
        }
    }
    __syncthreads();

    // -------- coalesced epilogue: thread owns column n, half the rows --------
    {
        const int colt = tid & 127;
        const int rbase = (tid >> 7) * 64;
        const int n = n0 + colt;
        const float bv = bias[n];
        if (EPI == 0) {
            const int sec = n >> 10;          // 0=q, 1=k, 2=v
            const int e = n & 1023;
            const int h = e >> 6;
            const int d = e & 63;
            const float sc = (sec == 0) ? SCALING : 1.0f;
            float* dstb = (sec == 0) ? g_q : (sec == 1) ? g_k : g_v;
#pragma unroll 4
            for (int rr = 0; rr < 64; rr++) {
                const int row = rbase + rr;
                const int m = m0 + row;
                const int b = m & (B_DIM - 1);
                const int l = m >> 3;
                float val = (sf[row * 129 + colt] + bv) * sc;
                dstb[((size_t)(b * H_DIM + h) * L_DIM + l) * HD + d] = val;
            }
        } else {
#pragma unroll 4
            for (int rr = 0; rr < 64; rr++) {
                const int row = rbase + rr;
                const int m = m0 + row;
                out[(size_t)m * E_DIM + n] = sf[row * 129 + colt] + bv;
            }
        }
    }
}

// ---------------------------------------------------------------------------
// Flash attention (fp32, online softmax). Epilogue now emits bf16 hi/lo
// directly (feeds out-projection GEMM; saves a 64MB-traffic split pass).
// ---------------------------------------------------------------------------
__global__ __launch_bounds__(256) void attn_kernel()
{
    __shared__ float Qt[64][64];
    __shared__ float KP[64][64];
    __shared__ float Vs[64][64];

    const int bh = blockIdx.x;
    const int q0 = blockIdx.y * 64;
    const int t  = threadIdx.x;
    const int tx = t & 15;
    const int ty = t >> 4;

    const float* Qg = g_q + ((size_t)bh * L_DIM + q0) * HD;
    const float* Kg = g_k + (size_t)bh * L_DIM * HD;
    const float* Vg = g_v + (size_t)bh * L_DIM * HD;

#pragma unroll
    for (int u = 0; u < 4; u++) {
        int f   = t + 256 * u;
        int row = f >> 4;
        int d0  = (f & 15) * 4;
        float4 v = *(const float4*)(Qg + (size_t)row * HD + d0);
        Qt[d0 + 0][row] = v.x; Qt[d0 + 1][row] = v.y;
        Qt[d0 + 2][row] = v.z; Qt[d0 + 3][row] = v.w;
    }

    float m_i[4], l_i[4], O[4][4];
#pragma unroll
    for (int i = 0; i < 4; i++) {
        m_i[i] = -1e30f; l_i[i] = 0.0f;
#pragma unroll
        for (int j = 0; j < 4; j++) O[i][j] = 0.0f;
    }

    for (int kt = 0; kt < L_DIM / 64; kt++) {
        __syncthreads();

#pragma unroll
        for (int u = 0; u < 4; u++) {
            int f   = t + 256 * u;
            int row = f >> 4;
            int d0  = (f & 15) * 4;
            const float* kp = Kg + ((size_t)(kt * 64 + row)) * HD + d0;
            float4 v = *(const float4*)kp;
            KP[d0 + 0][row] = v.x; KP[d0 + 1][row] = v.y;
            KP[d0 + 2][row] = v.z; KP[d0 + 3][row] = v.w;
            const float* vp = Vg + ((size_t)(kt * 64 + row)) * HD + d0;
            *(float4*)&Vs[row][d0] = *(const float4*)vp;
        }
        __syncthreads();

        float s[4][4];
#pragma unroll
        for (int i = 0; i < 4; i++)
#pragma unroll
            for (int j = 0; j < 4; j++) s[i][j] = 0.0f;

#pragma unroll
        for (int kk = 0; kk < 64; kk++) {
            float4 qa = *(const float4*)&Qt[kk][ty * 4];
            float4 kb = *(const float4*)&KP[kk][tx * 4];
            const float qv[4] = {qa.x, qa.y, qa.z, qa.w};
            const float kv[4] = {kb.x, kb.y, kb.z, kb.w};
#pragma unroll
            for (int i = 0; i < 4; i++)
#pragma unroll
                for (int j = 0; j < 4; j++) s[i][j] = fmaf(qv[i], kv[j], s[i][j]);
        }

#pragma unroll
        for (int i = 0; i < 4; i++) {
            float lm = fmaxf(fmaxf(s[i][0], s[i][1]), fmaxf(s[i][2], s[i][3]));
#pragma unroll
            for (int off = 8; off >= 1; off >>= 1)
                lm = fmaxf(lm, __shfl_xor_sync(0xffffffffu, lm, off));
            float mn = fmaxf(m_i[i], lm);
            float corr = __expf(m_i[i] - mn);
            float rs = 0.0f;
#pragma unroll
            for (int j = 0; j < 4; j++) {
                s[i][j] = __expf(s[i][j] - mn);
                rs += s[i][j];
            }
#pragma unroll
            for (int off = 8; off >= 1; off >>= 1)
                rs += __shfl_xor_sync(0xffffffffu, rs, off);
            l_i[i] = l_i[i] * corr + rs;
            m_i[i] = mn;
#pragma unroll
            for (int j = 0; j < 4; j++) O[i][j] *= corr;
        }

        __syncthreads();

#pragma unroll
        for (int i = 0; i < 4; i++)
#pragma unroll
            for (int j = 0; j < 4; j++)
                KP[tx * 4 + j][ty * 4 + i] = s[i][j];
        __syncthreads();

#pragma unroll
        for (int j64 = 0; j64 < 64; j64++) {
            float4 pa = *(const float4*)&KP[j64][ty * 4];
            float4 vb = *(const float4*)&Vs[j64][tx * 4];
            const float pv[4] = {pa.x, pa.y, pa.z, pa.w};
            const float vv[4] = {vb.x, vb.y, vb.z, vb.w};
#pragma unroll
            for (int i = 0; i < 4; i++)
#pragma unroll
                for (int j = 0; j < 4; j++) O[i][j] = fmaf(pv[i], vv[j], O[i][j]);
        }
    }

    // Epilogue: normalize + bf16 hi/lo split, att[m][e] with m=l*B+b, e=h*64+d
    const int b = bh >> 4;
    const int h = bh & 15;
#pragma unroll
    for (int i = 0; i < 4; i++) {
        float inv = 1.0f / l_i[i];
        int l = q0 + ty * 4 + i;
        size_t idx = ((size_t)l * B_DIM + b) * E_DIM + h * HD + tx * 4;
        float v[4];
#pragma unroll
        for (int j = 0; j < 4; j++) v[j] = O[i][j] * inv;
        __nv_bfloat16 hh[4];
        __nv_bfloat16 ll[4];
#pragma unroll
        for (int j = 0; j < 4; j++) {
            hh[j] = __float2bfloat16(v[j]);
            ll[j] = __float2bfloat16(v[j] - __bfloat162float(hh[j]));
        }
        *(__nv_bfloat162*)(g_ah + idx)     = __nv_bfloat162(hh[0], hh[1]);
        *(__nv_bfloat162*)(g_ah + idx + 2) = __nv_bfloat162(hh[2], hh[3]);
        *(__nv_bfloat162*)(g_al + idx)     = __nv_bfloat162(ll[0], ll[1]);
        *(__nv_bfloat162*)(g_al + idx + 2) = __nv_bfloat162(ll[2], ll[3]);
    }
}

// ---------------------------------------------------------------------------
// Inputs (metadata order): x, in_proj_weight, in_proj_bias, out_proj_weight,
//                          out_proj_bias, num_heads
// ---------------------------------------------------------------------------
extern "C" void kernel_launch(void* const* d_in, const int* in_sizes, int n_in,
                              void* d_out, int out_size)
{
    const float* x    = (const float*)d_in[0];
    const float* wqkv = (const float*)d_in[1];
    const float* bqkv = (const float*)d_in[2];
    const float* wout = (const float*)d_in[3];
    const float* bout = (const float*)d_in[4];
    float* out = (float*)d_out;

    cudaFuncSetAttribute(hmma_gemm_kernel<0>,
                         cudaFuncAttributeMaxDynamicSharedMemorySize, GEMM_SMEM);
    cudaFuncSetAttribute(hmma_gemm_kernel<1>,
                         cudaFuncAttributeMaxDynamicSharedMemorySize, GEMM_SMEM);

    __nv_bfloat16 *xh, *xl, *w1h, *w1l, *ah, *al, *w2h, *w2l;
    cudaGetSymbolAddress((void**)&xh,  g_xh);
    cudaGetSymbolAddress((void**)&xl,  g_xl);
    cudaGetSymbolAddress((void**)&w1h, g_w1h);
    cudaGetSymbolAddress((void**)&w1l, g_w1l);
    cudaGetSymbolAddress((void**)&ah,  g_ah);
    cudaGetSymbolAddress((void**)&al,  g_al);
    cudaGetSymbolAddress((void**)&w2h, g_w2h);
    cudaGetSymbolAddress((void**)&w2l, g_w2l);

    // 1) split inputs to bf16 hi/lo
    {
        int n = M_DIM * E_DIM;
        split_kernel<<<(n + 255) / 256, 256>>>(x, xh, xl, n);
        n = NQKV * E_DIM;
        split_kernel<<<(n + 255) / 256, 256>>>(wqkv, w1h, w1l, n);
        n = E_DIM * E_DIM;
        split_kernel<<<(n + 255) / 256, 256>>>(wout, w2h, w2l, n);
    }

    // 2) QKV projection on tensor cores (HMMA), scatter to head-major q/k/v
    {
        dim3 grid(NQKV / 128, M_DIM / 128);   // (24, 64)
        hmma_gemm_kernel<0><<<grid, 256, GEMM_SMEM>>>(xh, xl, w1h, w1l,
                                                      bqkv, nullptr, E_DIM);
    }

    // 3) Attention (fp32 SIMT), epilogue emits bf16 hi/lo
    {
        dim3 grid(BH, L_DIM / 64);            // (128, 16)
        attn_kernel<<<grid, 256>>>();
    }

    // 4) Output projection on tensor cores (HMMA) -> d_out
    {
        dim3 grid(E_DIM / 128, M_DIM / 128);  // (8, 64)
        hmma_gemm_kernel<1><<<grid, 256, GEMM_SMEM>>>(ah, al, w2h, w2l,
                                                      bout, out, E_DIM);
    }
}